// round 14
// baseline (speedup 1.0000x reference)
#include <cuda_runtime.h>
#include <cuda_fp16.h>
#include <cstdint>

// ---------------- problem constants ----------------
#define TOKENS  32
#define KDIM    8192
#define NDIM    28672
#define KSPLIT  2
#define NTILE   128
#define KTILE   128                            // one quant group per k-tile
#define TILES   (KDIM / KSPLIT / KTILE)        // 32
#define THREADS 128

// fp16 PERMUTED copy of x (pairs (x0,x4)(x1,x5)(x2,x6)(x3,x7) per 8-group)
__device__ __half g_xh[(size_t)TOKENS * KDIM];
// split-K fp32 scratch
__device__ float  g_scratch[KSPLIT][(size_t)NDIM * TOKENS];

// ---------------- helpers ----------------
__device__ __forceinline__ uint32_t smem_u32(const void* p) {
    uint32_t a;
    asm("{ .reg .u64 t; cvta.to.shared.u64 t, %1; cvt.u32.u64 %0, t; }" : "=r"(a) : "l"(p));
    return a;
}
#define LDMX4(r0, r1, r2, r3, addr) \
    asm volatile("ldmatrix.sync.aligned.m8n8.x4.shared.b16 {%0, %1, %2, %3}, [%4];" \
        : "=r"(r0), "=r"(r1), "=r"(r2), "=r"(r3) : "r"(addr))
#define MMA16816(c0, c1, c2, c3, a0, a1, a2, a3, b0, b1) \
    asm volatile("mma.sync.aligned.m16n8k16.row.col.f32.f16.f16.f32 " \
        "{%0,%1,%2,%3}, {%4,%5,%6,%7}, {%8,%9}, {%0,%1,%2,%3};" \
        : "+f"(c0), "+f"(c1), "+f"(c2), "+f"(c3) \
        : "r"(a0), "r"(a1), "r"(a2), "r"(a3), "r"(b0), "r"(b1))
// (w & 0x000F000F) | 0x64006400  -> half2 (1024+q_p, 1024+q_{p+4})
#define LOP3_EXT(d, a) \
    asm("lop3.b32 %0, %1, 0x000F000F, 0x64006400, 0xEA;" : "=r"(d) : "r"(a))
// 16B gmem -> smem async copy
#define CP_ASYNC16(dst, src) \
    asm volatile("cp.async.ca.shared.global [%0], [%1], 16;" \
        :: "r"(dst), "l"(src) : "memory")
#define CP_ASYNC_COMMIT() asm volatile("cp.async.commit_group;" ::: "memory")
#define CP_ASYNC_WAIT0()  asm volatile("cp.async.wait_group 0;" ::: "memory")

__device__ __forceinline__ __half2 u2h2(uint32_t v) {
    __half2 h; *reinterpret_cast<uint32_t*>(&h) = v; return h;
}
__device__ __forceinline__ uint32_t h22u(__half2 h) {
    return *reinterpret_cast<uint32_t*>(&h);
}

// ---------------- x convert kernel: f32 -> fp16, PAIR-PERMUTED ----------------
// For each 8-element k-group: store (x0,x4),(x1,x5),(x2,x6),(x3,x7) — the
// half order the A-dequant LOP3 produces, so the permutation cancels in mma.
__global__ void __launch_bounds__(256)
xconvert_kernel(const float* __restrict__ x)
{
    const int i = (blockIdx.x * 256 + threadIdx.x) * 8;
    const float4 a = *reinterpret_cast<const float4*>(x + i);
    const float4 b = *reinterpret_cast<const float4*>(x + i + 4);
    uint4 r;
    r.x = h22u(__floats2half2_rn(a.x, b.x));   // (x0, x4)
    r.y = h22u(__floats2half2_rn(a.y, b.y));   // (x1, x5)
    r.z = h22u(__floats2half2_rn(a.z, b.z));   // (x2, x6)
    r.w = h22u(__floats2half2_rn(a.w, b.w));   // (x3, x7)
    *reinterpret_cast<uint4*>(&g_xh[i]) = r;
}

// ---------------- main GEMM kernel: register-direct A dequant ----------------
// CTA = 128 threads = 4 warps; tile = 128 features x 128 k (one quant group).
// A (weights) NEVER touches SMEM: each lane LDGs the packed words its own
// mma A-fragments need (4-way duplicated addresses coalesce via broadcast),
// dequants with one shifted LOP3 per fragment into (q_p, q_{p+4}) pairs.
// X is pre-permuted identically, staged via cp.async into a double-buffered
// 2x8KB SMEM tile and read with ldmatrix (validated path, unchanged).
__global__ void __launch_bounds__(THREADS, 4)
exllama_gemm_kernel(const uint32_t* __restrict__ qw,
                    const uint32_t* __restrict__ qz,
                    const float* __restrict__ sc)
{
    __shared__ __align__(16) uint32_t Xs[2][2048];   // 2 x 8KB

    const int tid = threadIdx.x;
    const int w   = tid >> 5;
    const int l   = tid & 31;
    const int n0  = blockIdx.x * NTILE;
    const int ks  = blockIdx.y;

    const int warpbase = n0 + w * 32;
    const int fr = l >> 2;               // fragment row within 8 (0..7)
    const int sh = (l & 3) * 4;          // nibble-pair shift (k-pair select)
    const int xt0 = tid >> 4;            // X staging: token for i-step
    const int xc  = tid & 15;            // X staging: 16B chunk index

    const uint32_t xs0 = smem_u32(&Xs[0][0]);

    // lane's qweight base: feature column warpbase + fr (+8m via offset)
    const uint32_t* qwl = qw + warpbase + fr;
    const float*    scl = sc + warpbase + fr;

    float acc[2][4][4];
#pragma unroll
    for (int f = 0; f < 2; ++f)
#pragma unroll
        for (int tg = 0; tg < 4; ++tg)
#pragma unroll
            for (int i = 0; i < 4; ++i) acc[f][tg][i] = 0.f;

    const int g0    = ks * TILES;
    const int glast = g0 + TILES - 1;

    // rolling qword pipeline: slot = j & 3, 8 words per j-batch
    uint32_t q[4][8];
    // per-tile meta (current + prefetched next)
    uint4 zwc, zwn;
    float s_c[4], s_n[4];

    auto load_meta = [&](int g, uint4& zw, float* s) {
        zw = *reinterpret_cast<const uint4*>(
            qz + (size_t)g * (NDIM / 8) + (warpbase >> 3));
#pragma unroll
        for (int m = 0; m < 4; ++m)
            s[m] = scl[(size_t)g * NDIM + 8 * m];
    };
    auto cp_x = [&](int g, int buf) {
        const uint32_t xb = xs0 + (uint32_t)buf * 8192u;
#pragma unroll
        for (int i = 0; i < 4; ++i) {
            const int t = xt0 + i * 8;
            CP_ASYNC16(xb + (uint32_t)t * 256u + (uint32_t)(((xc ^ (t & 7)) << 4)),
                       &g_xh[(size_t)t * KDIM + (size_t)g * KTILE + xc * 8]);
        }
        CP_ASYNC_COMMIT();
    };

    // ---- prologue ----
    load_meta(g0, zwc, s_c);
    cp_x(g0, 0);
#pragma unroll
    for (int j = 0; j < 4; ++j)          // batches j=0..3 of tile 0
#pragma unroll
        for (int r = 0; r < 2; ++r)
#pragma unroll
            for (int m = 0; m < 4; ++m)
                q[j][r * 4 + m] =
                    qwl[(size_t)(g0 * 16 + 2 * j + r) * NDIM + 8 * m];

    const int t_a = (l & 7) + ((l >> 4) & 1) * 8;    // B ldmatrix token row

#pragma unroll 1
    for (int it = 0; it < TILES; ++it) {
        const int g  = g0 + it;
        const int gn = (g + 1 <= glast) ? g + 1 : glast;

        // per-tile dequant constants from prefetched meta
        __half2 zc2[4], s2[4];
        const uint32_t zw4[4] = { zwc.x, zwc.y, zwc.z, zwc.w };
#pragma unroll
        for (int m = 0; m < 4; ++m) {
            const uint32_t z1 = ((zw4[m] >> (fr * 4)) & 15u) + 1u;
            zc2[m] = __half2half2(__ushort_as_half((unsigned short)(0x6400u + z1)));
            s2[m]  = __half2half2(__float2half(s_c[m]));
        }

        // prefetch next tile's meta
        load_meta(gn, zwn, s_n);

        CP_ASYNC_WAIT0();
        __syncthreads();                 // X(it) ready; X buf (it+1)&1 free
        if (it + 1 < TILES) cp_x(g + 1, (it + 1) & 1);

        const uint32_t xb = xs0 + (uint32_t)(it & 1) * 8192u;

#pragma unroll
        for (int j = 0; j < 8; ++j) {
            const int s = j & 3;
            // ---- B fragments (tokens 0-31) via ldmatrix ----
            uint32_t b[8];
            const int cc = 2 * j + ((l >> 3) & 1);
            const uint32_t ba = xb + (uint32_t)t_a * 256u
                              + (uint32_t)(((cc ^ (t_a & 7)) << 4));
            LDMX4(b[0], b[1], b[2], b[3], ba);
            LDMX4(b[4], b[5], b[6], b[7], ba + 16 * 256);

            // ---- dequant 8 A-fragments from q[s] ----
            // q[s][r*4+m]: r = chunk (2j, 2j+1), m = feature block (+8m)
            uint32_t fa[2][4];
#pragma unroll
            for (int f = 0; f < 2; ++f) {
                const int m0 = f * 2, m1 = f * 2 + 1;
                {   uint32_t p; LOP3_EXT(p, q[s][m0] >> sh);
                    fa[f][0] = h22u(__hmul2(__hsub2(u2h2(p), zc2[m0]), s2[m0])); }
                {   uint32_t p; LOP3_EXT(p, q[s][m1] >> sh);
                    fa[f][1] = h22u(__hmul2(__hsub2(u2h2(p), zc2[m1]), s2[m1])); }
                {   uint32_t p; LOP3_EXT(p, q[s][4 + m0] >> sh);
                    fa[f][2] = h22u(__hmul2(__hsub2(u2h2(p), zc2[m0]), s2[m0])); }
                {   uint32_t p; LOP3_EXT(p, q[s][4 + m1] >> sh);
                    fa[f][3] = h22u(__hmul2(__hsub2(u2h2(p), zc2[m1]), s2[m1])); }
            }

            // ---- reload slot with batch j+4 (this tile j<4, else next tile) ----
            {
                const int jj = (j < 4) ? (j + 4) : (j - 4);
                const int gg = (j < 4) ? g : gn;
#pragma unroll
                for (int r = 0; r < 2; ++r)
#pragma unroll
                    for (int m = 0; m < 4; ++m)
                        q[s][r * 4 + m] =
                            qwl[(size_t)(gg * 16 + 2 * jj + r) * NDIM + 8 * m];
            }

            // ---- 8 mma ----
#pragma unroll
            for (int f = 0; f < 2; ++f)
#pragma unroll
                for (int tg = 0; tg < 4; ++tg)
                    MMA16816(acc[f][tg][0], acc[f][tg][1], acc[f][tg][2], acc[f][tg][3],
                             fa[f][0], fa[f][1], fa[f][2], fa[f][3],
                             b[2 * tg], b[2 * tg + 1]);
        }

        zwc = zwn;
#pragma unroll
        for (int m = 0; m < 4; ++m) s_c[m] = s_n[m];
    }

    // ---- write fp32 partials: scratch[ks][n * TOKENS + t] ----
#pragma unroll
    for (int f = 0; f < 2; ++f) {
        const int nb = n0 + w * 32 + f * 16 + fr;
#pragma unroll
        for (int tg = 0; tg < 4; ++tg) {
            const int tok = tg * 8 + (l & 3) * 2;
            *reinterpret_cast<float2*>(&g_scratch[ks][(size_t)nb * TOKENS + tok]) =
                make_float2(acc[f][tg][0], acc[f][tg][1]);
            *reinterpret_cast<float2*>(&g_scratch[ks][(size_t)(nb + 8) * TOKENS + tok]) =
                make_float2(acc[f][tg][2], acc[f][tg][3]);
        }
    }
}

// ---------------- split-sum + bias + transpose epilogue (f32 out) ----------------
__global__ void __launch_bounds__(256)
reduce_bias_kernel(const float* __restrict__ bias, float* __restrict__ out)
{
    __shared__ float s[64 * 33];
    const int n0  = blockIdx.x * 64;
    const int tid = threadIdx.x;
#pragma unroll
    for (int i = 0; i < 8; ++i) {
        const int v  = tid + i * 256;
        const int nl = v >> 5, t = v & 31;
        const size_t idx = (size_t)(n0 + nl) * TOKENS + t;
        s[nl * 33 + t] = g_scratch[0][idx] + g_scratch[1][idx];
    }
    __syncthreads();
#pragma unroll
    for (int i = 0; i < 8; ++i) {
        const int v  = tid + i * 256;
        const int t = v >> 6, nl = v & 63;
        // ref-matched rounding: h16(acc) + h16(bias) in fp16, then widen
        const __half h = __hadd(__float2half(s[nl * 33 + t]),
                                __float2half(bias[n0 + nl]));
        out[(size_t)t * NDIM + n0 + nl] = __half2float(h);
    }
}

// ---------------- launch ----------------
// Bind inputs by element count (all five unique); fall back to positional.
//   x: 262144  qweight: 29360128  qzeros: 229376  scales: 1835008  bias: 28672
extern "C" void kernel_launch(void* const* d_in, const int* in_sizes, int n_in,
                              void* d_out, int out_size)
{
    const float*    x    = nullptr;
    const uint32_t* qw   = nullptr;
    const uint32_t* qz   = nullptr;
    const float*    sc   = nullptr;
    const float*    bias = nullptr;

    for (int i = 0; i < n_in; ++i) {
        switch (in_sizes[i]) {
            case 262144:   x    = (const float*)   d_in[i]; break;
            case 29360128: qw   = (const uint32_t*)d_in[i]; break;
            case 229376:   qz   = (const uint32_t*)d_in[i]; break;
            case 1835008:  sc   = (const float*)   d_in[i]; break;
            case 28672:    bias = (const float*)   d_in[i]; break;
            default: break;
        }
    }
    if (!x || !qw || !qz || !sc || !bias) {   // positional fallback
        x    = (const float*)   d_in[0];
        qw   = (const uint32_t*)d_in[1];
        qz   = (const uint32_t*)d_in[2];
        sc   = (const float*)   d_in[3];
        bias = (const float*)   d_in[4];
    }
    float* out = (float*)d_out;

    xconvert_kernel<<<TOKENS * KDIM / (256 * 8), 256>>>(x);
    dim3 grid(NDIM / NTILE, KSPLIT);
    exllama_gemm_kernel<<<grid, THREADS>>>(qw, qz, sc);
    reduce_bias_kernel<<<NDIM / 64, 256>>>(bias, out);
}